// round 1
// baseline (speedup 1.0000x reference)
#include <cuda_runtime.h>
#include <cuda_bf16.h>
#include <math.h>

// Problem constants (fixed by the dataset)
#define NND   100000
#define NED   1600000
#define DD    128

// ---------------- device scratch (no allocations allowed) ----------------
__device__ float g_z[(size_t)NND * DD];      // z = h @ W        (51.2 MB)
__device__ float g_ssrc[NND];                // z . a[:128]
__device__ float g_sdst[NND];                // z . a[128:]
__device__ int   g_count[NND];               // histogram of dst
__device__ int   g_cursor[NND];              // scatter cursors
__device__ int   g_off[NND + 1];             // CSR offsets by dst
__device__ int   g_srcs[NED];                // CSR: src node per slot

// ---------------- GEMM: z = h @ W  (128x128x32 tile, 8x8 microtile) ------
#define BM 128
#define BK 32

__global__ __launch_bounds__(256, 2)
void gemm_kernel(const float* __restrict__ h, const float* __restrict__ W, int n) {
    __shared__ float As[BM][BK + 1];   // padded
    __shared__ float Bs[BK][DD];

    int tid = threadIdx.x;
    int tx = tid & 15;         // 0..15 -> 8 output cols each
    int ty = tid >> 4;         // 0..15 -> 8 output rows each
    int block_row = blockIdx.x * BM;

    float acc[8][8];
#pragma unroll
    for (int i = 0; i < 8; i++)
#pragma unroll
        for (int j = 0; j < 8; j++) acc[i][j] = 0.f;

    for (int k0 = 0; k0 < DD; k0 += BK) {
        // load A tile: 128x32 floats, 16 per thread, coalesced
#pragma unroll
        for (int t = 0; t < 16; t++) {
            int idx = tid + t * 256;
            int r = idx >> 5;          // 0..127
            int c = idx & 31;          // 0..31
            int grow = block_row + r;
            As[r][c] = (grow < n) ? h[(size_t)grow * DD + k0 + c] : 0.f;
        }
        // load B tile: 32x128 floats
#pragma unroll
        for (int t = 0; t < 16; t++) {
            int idx = tid + t * 256;
            int r = idx >> 7;          // 0..31
            int c = idx & 127;         // 0..127
            Bs[r][c] = W[(size_t)(k0 + r) * DD + c];
        }
        __syncthreads();

#pragma unroll
        for (int kk = 0; kk < BK; kk++) {
            float a[8], b[8];
#pragma unroll
            for (int i = 0; i < 8; i++) a[i] = As[ty * 8 + i][kk];
            // vector reads of B row
            float4 b0 = reinterpret_cast<const float4*>(&Bs[kk][0])[tx * 2];
            float4 b1 = reinterpret_cast<const float4*>(&Bs[kk][0])[tx * 2 + 1];
            b[0] = b0.x; b[1] = b0.y; b[2] = b0.z; b[3] = b0.w;
            b[4] = b1.x; b[5] = b1.y; b[6] = b1.z; b[7] = b1.w;
#pragma unroll
            for (int i = 0; i < 8; i++)
#pragma unroll
                for (int j = 0; j < 8; j++)
                    acc[i][j] = fmaf(a[i], b[j], acc[i][j]);
        }
        __syncthreads();
    }

#pragma unroll
    for (int i = 0; i < 8; i++) {
        int row = block_row + ty * 8 + i;
        if (row < n) {
            float4* zr = reinterpret_cast<float4*>(&g_z[(size_t)row * DD]);
            float4 v0 = make_float4(acc[i][0], acc[i][1], acc[i][2], acc[i][3]);
            float4 v1 = make_float4(acc[i][4], acc[i][5], acc[i][6], acc[i][7]);
            zr[tx * 2]     = v0;
            zr[tx * 2 + 1] = v1;
        }
    }
}

// ---------------- per-node attention scores: warp per node ---------------
__global__ void sdot_kernel(const float* __restrict__ attn, int n) {
    int warp = (blockIdx.x * blockDim.x + threadIdx.x) >> 5;
    int lane = threadIdx.x & 31;
    if (warp >= n) return;
    const float* zr = &g_z[(size_t)warp * DD];
    float a1 = 0.f, a2 = 0.f;
#pragma unroll
    for (int k = 0; k < 4; k++) {
        float zv = zr[lane + 32 * k];
        a1 = fmaf(zv, attn[lane + 32 * k], a1);
        a2 = fmaf(zv, attn[DD + lane + 32 * k], a2);
    }
#pragma unroll
    for (int o = 16; o; o >>= 1) {
        a1 += __shfl_xor_sync(0xffffffff, a1, o);
        a2 += __shfl_xor_sync(0xffffffff, a2, o);
    }
    if (lane == 0) {
        g_ssrc[warp] = a1;
        g_sdst[warp] = a2;
    }
}

// ---------------- CSR build -----------------------------------------------
__global__ void zero_kernel(int n) {
    int i = blockIdx.x * blockDim.x + threadIdx.x;
    if (i < n) { g_count[i] = 0; g_cursor[i] = 0; }
}

__global__ void hist_kernel(const int* __restrict__ dst, int ne) {
    int e = blockIdx.x * blockDim.x + threadIdx.x;
    if (e < ne) atomicAdd(&g_count[dst[e]], 1);
}

__global__ void scan_kernel(int n) {
    __shared__ int sums[1024];
    int t = threadIdx.x;
    int chunk = (n + 1023) / 1024;
    int begin = t * chunk;
    int end = min(begin + chunk, n);
    int s = 0;
    for (int i = begin; i < end; i++) s += g_count[i];
    sums[t] = s;
    __syncthreads();
    // Hillis-Steele inclusive scan
    for (int off = 1; off < 1024; off <<= 1) {
        int x = 0;
        if (t >= off) x = sums[t - off];
        __syncthreads();
        sums[t] += x;
        __syncthreads();
    }
    int run = sums[t] - s;     // exclusive prefix for this thread's chunk
    for (int i = begin; i < end; i++) {
        g_off[i] = run;
        run += g_count[i];
    }
    if (t == 1023) g_off[n] = sums[1023];
}

__global__ void scatter_kernel(const int* __restrict__ src,
                               const int* __restrict__ dst, int ne) {
    int e = blockIdx.x * blockDim.x + threadIdx.x;
    if (e < ne) {
        int d = dst[e];
        int pos = g_off[d] + atomicAdd(&g_cursor[d], 1);
        g_srcs[pos] = src[e];
    }
}

// ---------------- aggregation: warp per dst node --------------------------
__global__ __launch_bounds__(256)
void aggregate_kernel(float* __restrict__ out, int n) {
    int warp = (blockIdx.x * blockDim.x + threadIdx.x) >> 5;
    int lane = threadIdx.x & 31;
    if (warp >= n) return;

    int start = g_off[warp];
    int end   = g_off[warp + 1];
    float* orow = out + (size_t)warp * DD;

    if (start == end) {
#pragma unroll
        for (int k = 0; k < 4; k++) orow[lane + 32 * k] = 0.f;
        return;
    }

    float sd = g_sdst[warp];

    // pass 1: max over incoming edges (lanes parallel over edges)
    float m = -INFINITY;
    for (int j = start + lane; j < end; j += 32) {
        float x = g_ssrc[g_srcs[j]] + sd;
        x = (x > 0.f) ? x : 0.01f * x;
        m = fmaxf(m, x);
    }
#pragma unroll
    for (int o = 16; o; o >>= 1) m = fmaxf(m, __shfl_xor_sync(0xffffffff, m, o));

    // pass 2: serial over edges; lanes split the 128-dim feature vector
    float denom = 0.f;
    float acc0 = 0.f, acc1 = 0.f, acc2 = 0.f, acc3 = 0.f;
#pragma unroll 2
    for (int j = start; j < end; j++) {
        int s = g_srcs[j];
        float x = g_ssrc[s] + sd;
        x = (x > 0.f) ? x : 0.01f * x;
        float w = __expf(x - m);
        denom += w;
        const float* zr = g_z + (size_t)s * DD;
        acc0 = fmaf(w, zr[lane],      acc0);
        acc1 = fmaf(w, zr[lane + 32], acc1);
        acc2 = fmaf(w, zr[lane + 64], acc2);
        acc3 = fmaf(w, zr[lane + 96], acc3);
    }
    float inv = 1.0f / denom;
    orow[lane]      = acc0 * inv;
    orow[lane + 32] = acc1 * inv;
    orow[lane + 64] = acc2 * inv;
    orow[lane + 96] = acc3 * inv;
}

// ---------------- launch ---------------------------------------------------
extern "C" void kernel_launch(void* const* d_in, const int* in_sizes, int n_in,
                              void* d_out, int out_size) {
    const float* h      = (const float*)d_in[0];
    const float* W      = (const float*)d_in[1];
    const float* attn_w = (const float*)d_in[2];
    const int*   esrc   = (const int*)d_in[3];
    const int*   edst   = (const int*)d_in[4];
    float* out = (float*)d_out;

    int n  = in_sizes[0] / DD;   // 100000
    int ne = in_sizes[3];        // 1600000

    // 1) z = h @ W
    gemm_kernel<<<(n + BM - 1) / BM, 256>>>(h, W, n);
    // 2) per-node attention scores
    sdot_kernel<<<(n * 32 + 255) / 256, 256>>>(attn_w, n);
    // 3) CSR build by dst
    zero_kernel<<<(n + 255) / 256, 256>>>(n);
    hist_kernel<<<(ne + 255) / 256, 256>>>(edst, ne);
    scan_kernel<<<1, 1024>>>(n);
    scatter_kernel<<<(ne + 255) / 256, 256>>>(esrc, edst, ne);
    // 4) softmax + weighted aggregation, warp per dst node
    aggregate_kernel<<<(n * 32 + 255) / 256, 256>>>(out, n);
}

// round 2
// speedup vs baseline: 1.0984x; 1.0984x over previous
#include <cuda_runtime.h>
#include <cuda_fp16.h>
#include <math.h>

// Problem constants (fixed by the dataset)
#define NND   100000
#define NED   1600000
#define DD    128

// ---------------- device scratch (no allocations allowed) ----------------
__device__ __half g_zh[(size_t)NND * DD];    // z in fp16 (25.6 MB) for the gather
__device__ float  g_ssrc[NND];               // z . a[:128]  (fp32, exact from acc)
__device__ float  g_sdst[NND];               // z . a[128:]
__device__ int    g_count[NND];              // histogram of dst
__device__ int    g_cursor[NND];             // scatter cursors
__device__ int    g_off[NND + 1];            // CSR offsets by dst
__device__ int    g_srcs[NED];               // CSR: src node per slot

// ---------------- GEMM: z = h @ W, fused sdot + fp16 store ---------------
#define BM 128
#define BK 32

__global__ __launch_bounds__(256, 2)
void gemm_kernel(const float* __restrict__ h, const float* __restrict__ W,
                 const float* __restrict__ attn, int n) {
    __shared__ float As[BM][BK + 1];   // padded
    __shared__ float Bs[BK][DD];

    int tid = threadIdx.x;
    int tx = tid & 15;         // 0..15 -> 8 output cols each (cols tx*8..tx*8+7)
    int ty = tid >> 4;         // 0..15 -> 8 output rows each
    int block_row = blockIdx.x * BM;

    float acc[8][8];
#pragma unroll
    for (int i = 0; i < 8; i++)
#pragma unroll
        for (int j = 0; j < 8; j++) acc[i][j] = 0.f;

    for (int k0 = 0; k0 < DD; k0 += BK) {
#pragma unroll
        for (int t = 0; t < 16; t++) {
            int idx = tid + t * 256;
            int r = idx >> 5;          // 0..127
            int c = idx & 31;          // 0..31
            int grow = block_row + r;
            As[r][c] = (grow < n) ? h[(size_t)grow * DD + k0 + c] : 0.f;
        }
#pragma unroll
        for (int t = 0; t < 16; t++) {
            int idx = tid + t * 256;
            int r = idx >> 7;          // 0..31
            int c = idx & 127;         // 0..127
            Bs[r][c] = W[(size_t)(k0 + r) * DD + c];
        }
        __syncthreads();

#pragma unroll
        for (int kk = 0; kk < BK; kk++) {
            float a[8], b[8];
#pragma unroll
            for (int i = 0; i < 8; i++) a[i] = As[ty * 8 + i][kk];
            float4 b0 = reinterpret_cast<const float4*>(&Bs[kk][0])[tx * 2];
            float4 b1 = reinterpret_cast<const float4*>(&Bs[kk][0])[tx * 2 + 1];
            b[0] = b0.x; b[1] = b0.y; b[2] = b0.z; b[3] = b0.w;
            b[4] = b1.x; b[5] = b1.y; b[6] = b1.z; b[7] = b1.w;
#pragma unroll
            for (int i = 0; i < 8; i++)
#pragma unroll
                for (int j = 0; j < 8; j++)
                    acc[i][j] = fmaf(a[i], b[j], acc[i][j]);
        }
        __syncthreads();
    }

    // preload attn weights for this thread's 8 columns
    float a1r[8], a2r[8];
#pragma unroll
    for (int j = 0; j < 8; j++) {
        a1r[j] = attn[tx * 8 + j];
        a2r[j] = attn[DD + tx * 8 + j];
    }

#pragma unroll
    for (int i = 0; i < 8; i++) {
        int row = block_row + ty * 8 + i;
        bool valid = (row < n);

        // fp16 store: 8 halves = one uint4 per thread, coalesced across tx
        if (valid) {
            __half2 p0 = __floats2half2_rn(acc[i][0], acc[i][1]);
            __half2 p1 = __floats2half2_rn(acc[i][2], acc[i][3]);
            __half2 p2 = __floats2half2_rn(acc[i][4], acc[i][5]);
            __half2 p3 = __floats2half2_rn(acc[i][6], acc[i][7]);
            uint4 u;
            u.x = *reinterpret_cast<unsigned*>(&p0);
            u.y = *reinterpret_cast<unsigned*>(&p1);
            u.z = *reinterpret_cast<unsigned*>(&p2);
            u.w = *reinterpret_cast<unsigned*>(&p3);
            reinterpret_cast<uint4*>(&g_zh[(size_t)row * DD])[tx] = u;
        }

        // fused attention-score partial dots (fp32, exact)
        float p1s = 0.f, p2s = 0.f;
#pragma unroll
        for (int j = 0; j < 8; j++) {
            p1s = fmaf(acc[i][j], a1r[j], p1s);
            p2s = fmaf(acc[i][j], a2r[j], p2s);
        }
        // reduce across the 16 tx-lanes of this row (lanes 0-15 / 16-31 disjoint)
#pragma unroll
        for (int o = 8; o; o >>= 1) {
            p1s += __shfl_xor_sync(0xffffffff, p1s, o);
            p2s += __shfl_xor_sync(0xffffffff, p2s, o);
        }
        if (valid && (tid & 15) == 0) {
            g_ssrc[row] = p1s;
            g_sdst[row] = p2s;
        }
    }
}

// ---------------- CSR build -----------------------------------------------
__global__ void zero_kernel(int n) {
    int i = blockIdx.x * blockDim.x + threadIdx.x;
    if (i < n) { g_count[i] = 0; g_cursor[i] = 0; }
}

__global__ void hist_kernel(const int* __restrict__ dst, int ne) {
    int e = blockIdx.x * blockDim.x + threadIdx.x;
    if (e < ne) atomicAdd(&g_count[dst[e]], 1);
}

__global__ void scan_kernel(int n) {
    __shared__ int sums[1024];
    int t = threadIdx.x;
    int chunk = (n + 1023) / 1024;
    int begin = t * chunk;
    int end = min(begin + chunk, n);
    int s = 0;
    for (int i = begin; i < end; i++) s += g_count[i];
    sums[t] = s;
    __syncthreads();
    for (int off = 1; off < 1024; off <<= 1) {
        int x = 0;
        if (t >= off) x = sums[t - off];
        __syncthreads();
        sums[t] += x;
        __syncthreads();
    }
    int run = sums[t] - s;
    for (int i = begin; i < end; i++) {
        g_off[i] = run;
        run += g_count[i];
    }
    if (t == 1023) g_off[n] = sums[1023];
}

__global__ void scatter_kernel(const int* __restrict__ src,
                               const int* __restrict__ dst, int ne) {
    int e = blockIdx.x * blockDim.x + threadIdx.x;
    if (e < ne) {
        int d = dst[e];
        int pos = g_off[d] + atomicAdd(&g_cursor[d], 1);
        g_srcs[pos] = src[e];
    }
}

// ---------------- aggregation: warp per dst node --------------------------
// Lane L owns output columns 4L..4L+3. Per edge each lane does ONE 8-byte
// load (4 halves) from the gathered z row -> 256B per warp per edge.
__global__ __launch_bounds__(256)
void aggregate_kernel(float* __restrict__ out, int n) {
    int warp = (blockIdx.x * blockDim.x + threadIdx.x) >> 5;
    int lane = threadIdx.x & 31;
    if (warp >= n) return;

    int start = g_off[warp];
    int end   = g_off[warp + 1];
    float4* orow = reinterpret_cast<float4*>(out + (size_t)warp * DD);

    if (start == end) {
        orow[lane] = make_float4(0.f, 0.f, 0.f, 0.f);
        return;
    }

    float sd = g_sdst[warp];

    // pass 1: max over incoming edges (lanes parallel over edges)
    float m = -INFINITY;
    for (int j = start + lane; j < end; j += 32) {
        float x = g_ssrc[g_srcs[j]] + sd;
        x = (x > 0.f) ? x : 0.01f * x;
        m = fmaxf(m, x);
    }
#pragma unroll
    for (int o = 16; o; o >>= 1) m = fmaxf(m, __shfl_xor_sync(0xffffffff, m, o));

    // pass 2: serial over edges; lanes split the 128-dim feature vector
    float denom = 0.f;
    float acc0 = 0.f, acc1 = 0.f, acc2 = 0.f, acc3 = 0.f;
#pragma unroll 4
    for (int j = start; j < end; j++) {
        int s = g_srcs[j];
        float x = g_ssrc[s] + sd;
        x = (x > 0.f) ? x : 0.01f * x;
        float w = __expf(x - m);
        denom += w;
        const uint2 hv = reinterpret_cast<const uint2*>(g_zh + (size_t)s * DD)[lane];
        __half2 h0 = *reinterpret_cast<const __half2*>(&hv.x);
        __half2 h1 = *reinterpret_cast<const __half2*>(&hv.y);
        float2 f0 = __half22float2(h0);
        float2 f1 = __half22float2(h1);
        acc0 = fmaf(w, f0.x, acc0);
        acc1 = fmaf(w, f0.y, acc1);
        acc2 = fmaf(w, f1.x, acc2);
        acc3 = fmaf(w, f1.y, acc3);
    }
    float inv = 1.0f / denom;
    orow[lane] = make_float4(acc0 * inv, acc1 * inv, acc2 * inv, acc3 * inv);
}

// ---------------- launch ---------------------------------------------------
extern "C" void kernel_launch(void* const* d_in, const int* in_sizes, int n_in,
                              void* d_out, int out_size) {
    const float* h      = (const float*)d_in[0];
    const float* W      = (const float*)d_in[1];
    const float* attn_w = (const float*)d_in[2];
    const int*   esrc   = (const int*)d_in[3];
    const int*   edst   = (const int*)d_in[4];
    float* out = (float*)d_out;

    int n  = in_sizes[0] / DD;   // 100000
    int ne = in_sizes[3];        // 1600000

    // 1) z = h @ W  (+ fused attention-score dots, fp16 z store)
    gemm_kernel<<<(n + BM - 1) / BM, 256>>>(h, W, attn_w, n);
    // 2) CSR build by dst
    zero_kernel<<<(n + 255) / 256, 256>>>(n);
    hist_kernel<<<(ne + 255) / 256, 256>>>(edst, ne);
    scan_kernel<<<1, 1024>>>(n);
    scatter_kernel<<<(ne + 255) / 256, 256>>>(esrc, edst, ne);
    // 3) softmax + weighted aggregation, warp per dst node
    aggregate_kernel<<<(n * 32 + 255) / 256, 256>>>(out, n);
}

// round 3
// speedup vs baseline: 1.5880x; 1.4457x over previous
#include <cuda_runtime.h>
#include <cuda_fp16.h>
#include <math.h>

// Problem constants (fixed by the dataset)
#define NND   100000
#define NED   1600000
#define DD    128
#define SCAN_B 256                       // counts per scan block
#define MAXSB  ((NND + SCAN_B - 1) / SCAN_B + 1)

// ---------------- device scratch (no allocations allowed) ----------------
__device__ __half g_zh[(size_t)NND * DD];    // z in fp16 (25.6 MB) for the gather
__device__ float  g_ssrc[NND];               // z . a[:128]  (fp32, exact from acc)
__device__ float  g_sdst[NND];               // z . a[128:]
__device__ int    g_count[NND];              // histogram of dst
__device__ int    g_cursor[NND];             // scatter cursors
__device__ int    g_off[NND + 1];            // CSR offsets by dst
__device__ int    g_srcs[NED];               // CSR: src node per slot
__device__ int    g_bsum[MAXSB];             // per-block count sums
__device__ int    g_bpre[MAXSB];             // exclusive prefix of block sums

// ---------------- GEMM: z = h @ W, fused sdot + fp16 store ---------------
#define BM 128
#define BK 32

__global__ __launch_bounds__(256, 2)
void gemm_kernel(const float* __restrict__ h, const float* __restrict__ W,
                 const float* __restrict__ attn, int n) {
    __shared__ float As[BM][BK + 1];   // padded
    __shared__ float Bs[BK][DD];

    int tid = threadIdx.x;
    int tx = tid & 15;         // 0..15 -> 8 output cols each (cols tx*8..tx*8+7)
    int ty = tid >> 4;         // 0..15 -> 8 output rows each
    int block_row = blockIdx.x * BM;

    float acc[8][8];
#pragma unroll
    for (int i = 0; i < 8; i++)
#pragma unroll
        for (int j = 0; j < 8; j++) acc[i][j] = 0.f;

    for (int k0 = 0; k0 < DD; k0 += BK) {
#pragma unroll
        for (int t = 0; t < 16; t++) {
            int idx = tid + t * 256;
            int r = idx >> 5;          // 0..127
            int c = idx & 31;          // 0..31
            int grow = block_row + r;
            As[r][c] = (grow < n) ? h[(size_t)grow * DD + k0 + c] : 0.f;
        }
#pragma unroll
        for (int t = 0; t < 16; t++) {
            int idx = tid + t * 256;
            int r = idx >> 7;          // 0..31
            int c = idx & 127;         // 0..127
            Bs[r][c] = W[(size_t)(k0 + r) * DD + c];
        }
        __syncthreads();

#pragma unroll
        for (int kk = 0; kk < BK; kk++) {
            float a[8], b[8];
#pragma unroll
            for (int i = 0; i < 8; i++) a[i] = As[ty * 8 + i][kk];
            float4 b0 = reinterpret_cast<const float4*>(&Bs[kk][0])[tx * 2];
            float4 b1 = reinterpret_cast<const float4*>(&Bs[kk][0])[tx * 2 + 1];
            b[0] = b0.x; b[1] = b0.y; b[2] = b0.z; b[3] = b0.w;
            b[4] = b1.x; b[5] = b1.y; b[6] = b1.z; b[7] = b1.w;
#pragma unroll
            for (int i = 0; i < 8; i++)
#pragma unroll
                for (int j = 0; j < 8; j++)
                    acc[i][j] = fmaf(a[i], b[j], acc[i][j]);
        }
        __syncthreads();
    }

    float a1r[8], a2r[8];
#pragma unroll
    for (int j = 0; j < 8; j++) {
        a1r[j] = attn[tx * 8 + j];
        a2r[j] = attn[DD + tx * 8 + j];
    }

#pragma unroll
    for (int i = 0; i < 8; i++) {
        int row = block_row + ty * 8 + i;
        bool valid = (row < n);

        if (valid) {
            __half2 p0 = __floats2half2_rn(acc[i][0], acc[i][1]);
            __half2 p1 = __floats2half2_rn(acc[i][2], acc[i][3]);
            __half2 p2 = __floats2half2_rn(acc[i][4], acc[i][5]);
            __half2 p3 = __floats2half2_rn(acc[i][6], acc[i][7]);
            uint4 u;
            u.x = *reinterpret_cast<unsigned*>(&p0);
            u.y = *reinterpret_cast<unsigned*>(&p1);
            u.z = *reinterpret_cast<unsigned*>(&p2);
            u.w = *reinterpret_cast<unsigned*>(&p3);
            reinterpret_cast<uint4*>(&g_zh[(size_t)row * DD])[tx] = u;
        }

        float p1s = 0.f, p2s = 0.f;
#pragma unroll
        for (int j = 0; j < 8; j++) {
            p1s = fmaf(acc[i][j], a1r[j], p1s);
            p2s = fmaf(acc[i][j], a2r[j], p2s);
        }
#pragma unroll
        for (int o = 8; o; o >>= 1) {
            p1s += __shfl_xor_sync(0xffffffff, p1s, o);
            p2s += __shfl_xor_sync(0xffffffff, p2s, o);
        }
        if (valid && (tid & 15) == 0) {
            g_ssrc[row] = p1s;
            g_sdst[row] = p2s;
        }
    }
}

// ---------------- CSR build -----------------------------------------------
__global__ void zero_kernel(int n) {
    int i = blockIdx.x * blockDim.x + threadIdx.x;
    if (i < n) { g_count[i] = 0; g_cursor[i] = 0; }
}

__global__ void hist_kernel(const int* __restrict__ dst, int ne) {
    int e = blockIdx.x * blockDim.x + threadIdx.x;
    if (e < ne) atomicAdd(&g_count[dst[e]], 1);
}

// Phase 1: per-block sums of g_count
__global__ __launch_bounds__(SCAN_B)
void blocksum_kernel(int n) {
    int b = blockIdx.x;
    int t = threadIdx.x;
    int i = b * SCAN_B + t;
    int v = (i < n) ? g_count[i] : 0;
#pragma unroll
    for (int o = 16; o; o >>= 1) v += __shfl_xor_sync(0xffffffff, v, o);
    __shared__ int ws[SCAN_B / 32];
    int lane = t & 31, w = t >> 5;
    if (lane == 0) ws[w] = v;
    __syncthreads();
    if (t == 0) {
        int s = 0;
#pragma unroll
        for (int k = 0; k < SCAN_B / 32; k++) s += ws[k];
        g_bsum[b] = s;
    }
}

// Phase 2: single-block scan of block sums (nb <= 1024)
__global__ __launch_bounds__(1024)
void bscan_kernel(int nb, int n) {
    __shared__ int s[1024];
    int t = threadIdx.x;
    int v = (t < nb) ? g_bsum[t] : 0;
    s[t] = v;
    __syncthreads();
    for (int o = 1; o < 1024; o <<= 1) {
        int x = (t >= o) ? s[t - o] : 0;
        __syncthreads();
        s[t] += x;
        __syncthreads();
    }
    if (t < nb) g_bpre[t] = s[t] - v;    // exclusive prefix
    if (t == 1023) g_off[n] = s[1023];   // total edge count
}

// Phase 3: per-block exclusive scan + block prefix -> g_off
__global__ __launch_bounds__(SCAN_B)
void scan_blocks_kernel(int n) {
    int b = blockIdx.x;
    int t = threadIdx.x;
    int i = b * SCAN_B + t;
    int v = (i < n) ? g_count[i] : 0;

    int lane = t & 31, w = t >> 5;
    int x = v;
#pragma unroll
    for (int o = 1; o < 32; o <<= 1) {
        int y = __shfl_up_sync(0xffffffff, x, o);
        if (lane >= o) x += y;
    }
    __shared__ int ws[SCAN_B / 32];
    if (lane == 31) ws[w] = x;
    __syncthreads();
    if (w == 0) {
        int s = (lane < SCAN_B / 32) ? ws[lane] : 0;
#pragma unroll
        for (int o = 1; o < SCAN_B / 32; o <<= 1) {
            int y = __shfl_up_sync(0xffffffff, s, o);
            if (lane >= o) s += y;
        }
        if (lane < SCAN_B / 32) ws[lane] = s;
    }
    __syncthreads();
    int incl = x + (w ? ws[w - 1] : 0);
    if (i < n) g_off[i] = g_bpre[b] + incl - v;
}

__global__ void scatter_kernel(const int* __restrict__ src,
                               const int* __restrict__ dst, int ne) {
    int e = blockIdx.x * blockDim.x + threadIdx.x;
    if (e < ne) {
        int d = dst[e];
        int pos = g_off[d] + atomicAdd(&g_cursor[d], 1);
        g_srcs[pos] = src[e];
    }
}

// ---------------- aggregation: warp per dst node --------------------------
__global__ __launch_bounds__(256)
void aggregate_kernel(float* __restrict__ out, int n) {
    int warp = (blockIdx.x * blockDim.x + threadIdx.x) >> 5;
    int lane = threadIdx.x & 31;
    if (warp >= n) return;

    int start = g_off[warp];
    int end   = g_off[warp + 1];
    float4* orow = reinterpret_cast<float4*>(out + (size_t)warp * DD);

    if (start == end) {
        orow[lane] = make_float4(0.f, 0.f, 0.f, 0.f);
        return;
    }

    float sd = g_sdst[warp];

    float m = -INFINITY;
    for (int j = start + lane; j < end; j += 32) {
        float x = g_ssrc[g_srcs[j]] + sd;
        x = (x > 0.f) ? x : 0.01f * x;
        m = fmaxf(m, x);
    }
#pragma unroll
    for (int o = 16; o; o >>= 1) m = fmaxf(m, __shfl_xor_sync(0xffffffff, m, o));

    float denom = 0.f;
    float acc0 = 0.f, acc1 = 0.f, acc2 = 0.f, acc3 = 0.f;
#pragma unroll 4
    for (int j = start; j < end; j++) {
        int s = g_srcs[j];
        float x = g_ssrc[s] + sd;
        x = (x > 0.f) ? x : 0.01f * x;
        float w = __expf(x - m);
        denom += w;
        const uint2 hv = reinterpret_cast<const uint2*>(g_zh + (size_t)s * DD)[lane];
        __half2 h0 = *reinterpret_cast<const __half2*>(&hv.x);
        __half2 h1 = *reinterpret_cast<const __half2*>(&hv.y);
        float2 f0 = __half22float2(h0);
        float2 f1 = __half22float2(h1);
        acc0 = fmaf(w, f0.x, acc0);
        acc1 = fmaf(w, f0.y, acc1);
        acc2 = fmaf(w, f1.x, acc2);
        acc3 = fmaf(w, f1.y, acc3);
    }
    float inv = 1.0f / denom;
    orow[lane] = make_float4(acc0 * inv, acc1 * inv, acc2 * inv, acc3 * inv);
}

// ---------------- launch ---------------------------------------------------
extern "C" void kernel_launch(void* const* d_in, const int* in_sizes, int n_in,
                              void* d_out, int out_size) {
    const float* h      = (const float*)d_in[0];
    const float* W      = (const float*)d_in[1];
    const float* attn_w = (const float*)d_in[2];
    const int*   esrc   = (const int*)d_in[3];
    const int*   edst   = (const int*)d_in[4];
    float* out = (float*)d_out;

    int n  = in_sizes[0] / DD;   // 100000
    int ne = in_sizes[3];        // 1600000
    int nb = (n + SCAN_B - 1) / SCAN_B;

    // 1) z = h @ W  (+ fused attention-score dots, fp16 z store)
    gemm_kernel<<<(n + BM - 1) / BM, 256>>>(h, W, attn_w, n);
    // 2) CSR build by dst (parallel 3-phase scan)
    zero_kernel<<<(n + 255) / 256, 256>>>(n);
    hist_kernel<<<(ne + 255) / 256, 256>>>(edst, ne);
    blocksum_kernel<<<nb, SCAN_B>>>(n);
    bscan_kernel<<<1, 1024>>>(nb, n);
    scan_blocks_kernel<<<nb, SCAN_B>>>(n);
    scatter_kernel<<<(ne + 255) / 256, 256>>>(esrc, edst, ne);
    // 3) softmax + weighted aggregation, warp per dst node
    aggregate_kernel<<<(n * 32 + 255) / 256, 256>>>(out, n);
}

// round 8
// speedup vs baseline: 2.4293x; 1.5298x over previous
#include <cuda_runtime.h>
#include <cuda_fp16.h>
#include <math.h>

// Problem constants (fixed by the dataset)
#define NND   100000
#define NED   1600000
#define DD    128
#define SCAN_B 256
#define MAXSB  ((NND + SCAN_B - 1) / SCAN_B + 1)

// ---------------- device scratch (no allocations allowed) ----------------
__device__ __half g_zh[(size_t)NND * DD];    // z in fp16 (25.6 MB) for the gather
__device__ float  g_ssrc[NND];
__device__ float  g_sdst[NND];
__device__ int    g_count[NND];
__device__ int    g_cursor[NND];
__device__ int    g_off[NND + 1];
__device__ int    g_srcs[NED];
__device__ int    g_bsum[MAXSB];
__device__ int    g_bpre[MAXSB];

// ---------------- tensor-core GEMM: z = h @ W (fp16 MMA, fused epilogue) --
// CTA tile: 128(M) x 128(N) x 128(K, fully resident). 8 warps, warp tile 32x64.
#define LDA 136            // padded row stride in halves (16B-aligned, conflict-free ldmatrix)
#define SMEM_HALVES (128 * LDA)
#define GEMM_SMEM_BYTES (2 * SMEM_HALVES * 2)

__device__ __forceinline__ unsigned smem_u32(const void* p) {
    return (unsigned)__cvta_generic_to_shared(p);
}

__global__ __launch_bounds__(256, 2)
void gemm_kernel(const float* __restrict__ h, const float* __restrict__ W,
                 const float* __restrict__ attn, int n) {
    extern __shared__ __half smem[];
    __half* Ah = smem;                 // h tile (fp16), later reused as z tile
    __half* Bh = smem + SMEM_HALVES;   // W (fp16), k-major [k][n]

    int tid = threadIdx.x;
    int lane = tid & 31;
    int warp = tid >> 5;
    int block_row = blockIdx.x * 128;

    // ---- load h tile (128x128 fp32 -> fp16) ----
#pragma unroll
    for (int t = 0; t < 16; t++) {
        int idx = tid + t * 256;       // 0..4095, each = one float4 (4 cols)
        int r = idx >> 5;              // 0..127
        int c4 = idx & 31;             // 0..31 (col/4)
        int grow = block_row + r;
        float4 v = (grow < n) ? reinterpret_cast<const float4*>(h + (size_t)grow * DD)[c4]
                              : make_float4(0.f, 0.f, 0.f, 0.f);
        __half2 p0 = __floats2half2_rn(v.x, v.y);
        __half2 p1 = __floats2half2_rn(v.z, v.w);
        *reinterpret_cast<__half2*>(&Ah[r * LDA + c4 * 4])     = p0;
        *reinterpret_cast<__half2*>(&Ah[r * LDA + c4 * 4 + 2]) = p1;
    }
    // ---- load W (128x128 fp32 -> fp16), k-major ----
#pragma unroll
    for (int t = 0; t < 16; t++) {
        int idx = tid + t * 256;
        int r = idx >> 5;
        int c4 = idx & 31;
        float4 v = reinterpret_cast<const float4*>(W + (size_t)r * DD)[c4];
        __half2 p0 = __floats2half2_rn(v.x, v.y);
        __half2 p1 = __floats2half2_rn(v.z, v.w);
        *reinterpret_cast<__half2*>(&Bh[r * LDA + c4 * 4])     = p0;
        *reinterpret_cast<__half2*>(&Bh[r * LDA + c4 * 4 + 2]) = p1;
    }
    __syncthreads();

    // ---- MMA mainloop ----
    int wm = warp >> 1;                // 0..3 -> rows wm*32..+32
    int wn = warp & 1;                 // 0..1 -> cols wn*64..+64
    float acc[2][8][4];
#pragma unroll
    for (int i = 0; i < 2; i++)
#pragma unroll
        for (int j = 0; j < 8; j++)
#pragma unroll
            for (int r = 0; r < 4; r++) acc[i][j][r] = 0.f;

#pragma unroll
    for (int ks = 0; ks < 8; ks++) {
        int k0 = ks * 16;
        // A fragments: two m16xk16 tiles
        unsigned af[2][4];
#pragma unroll
        for (int i = 0; i < 2; i++) {
            int r0 = wm * 32 + i * 16;
            int row = r0 + (lane & 15);
            int col = k0 + ((lane >> 4) << 3);
            unsigned addr = smem_u32(&Ah[row * LDA + col]);
            asm volatile("ldmatrix.sync.aligned.m8n8.x4.shared.b16 {%0,%1,%2,%3}, [%4];"
                         : "=r"(af[i][0]), "=r"(af[i][1]), "=r"(af[i][2]), "=r"(af[i][3])
                         : "r"(addr));
        }
        // B fragments: eight k16xn8 tiles (trans)
        unsigned bf[8][2];
#pragma unroll
        for (int j = 0; j < 8; j++) {
            int krow = k0 + (lane & 15);
            int ncol = wn * 64 + j * 8;
            unsigned addr = smem_u32(&Bh[krow * LDA + ncol]);
            asm volatile("ldmatrix.sync.aligned.m8n8.x2.trans.shared.b16 {%0,%1}, [%2];"
                         : "=r"(bf[j][0]), "=r"(bf[j][1])
                         : "r"(addr));
        }
#pragma unroll
        for (int i = 0; i < 2; i++)
#pragma unroll
            for (int j = 0; j < 8; j++) {
                asm volatile(
                    "mma.sync.aligned.m16n8k16.row.col.f32.f16.f16.f32 "
                    "{%0,%1,%2,%3}, {%4,%5,%6,%7}, {%8,%9}, {%0,%1,%2,%3};"
                    : "+f"(acc[i][j][0]), "+f"(acc[i][j][1]),
                      "+f"(acc[i][j][2]), "+f"(acc[i][j][3])
                    : "r"(af[i][0]), "r"(af[i][1]), "r"(af[i][2]), "r"(af[i][3]),
                      "r"(bf[j][0]), "r"(bf[j][1]));
            }
    }
    __syncthreads();   // done reading Ah/Bh

    // ---- accumulators -> fp16 z tile in smem (reuse Ah) ----
#pragma unroll
    for (int i = 0; i < 2; i++) {
        int r0 = wm * 32 + i * 16 + (lane >> 2);
#pragma unroll
        for (int j = 0; j < 8; j++) {
            int col = wn * 64 + j * 8 + ((lane & 3) << 1);
            *reinterpret_cast<__half2*>(&Ah[r0 * LDA + col]) =
                __floats2half2_rn(acc[i][j][0], acc[i][j][1]);
            *reinterpret_cast<__half2*>(&Ah[(r0 + 8) * LDA + col]) =
                __floats2half2_rn(acc[i][j][2], acc[i][j][3]);
        }
    }
    __syncthreads();

    // ---- coalesced global z store ----
#pragma unroll
    for (int t = 0; t < 8; t++) {
        int idx = tid + t * 256;       // 0..2047, each = 8 halves
        int r = idx >> 4;
        int seg = idx & 15;
        int grow = block_row + r;
        if (grow < n) {
            uint4 v = *reinterpret_cast<const uint4*>(&Ah[r * LDA + seg * 8]);
            reinterpret_cast<uint4*>(&g_zh[(size_t)grow * DD])[seg] = v;
        }
    }

    // ---- per-row attention dots (16 rows per warp) ----
    float4 a1 = reinterpret_cast<const float4*>(attn)[lane];        // cols lane*4..+3
    float4 a2 = reinterpret_cast<const float4*>(attn + DD)[lane];
#pragma unroll
    for (int rr = 0; rr < 16; rr++) {
        int r = warp * 16 + rr;
        int grow = block_row + r;
        const __half2 z0 = *reinterpret_cast<const __half2*>(&Ah[r * LDA + lane * 4]);
        const __half2 z1 = *reinterpret_cast<const __half2*>(&Ah[r * LDA + lane * 4 + 2]);
        float2 f0 = __half22float2(z0);
        float2 f1 = __half22float2(z1);
        float s1 = f0.x * a1.x + f0.y * a1.y + f1.x * a1.z + f1.y * a1.w;
        float s2 = f0.x * a2.x + f0.y * a2.y + f1.x * a2.z + f1.y * a2.w;
#pragma unroll
        for (int o = 16; o; o >>= 1) {
            s1 += __shfl_xor_sync(0xffffffff, s1, o);
            s2 += __shfl_xor_sync(0xffffffff, s2, o);
        }
        if (lane == 0 && grow < n) {
            g_ssrc[grow] = s1;
            g_sdst[grow] = s2;
        }
    }
}

// ---------------- CSR build -----------------------------------------------
__global__ void zero_kernel(int n) {
    int i = blockIdx.x * blockDim.x + threadIdx.x;
    if (i < n) g_count[i] = 0;
}

__global__ void hist_kernel(const int* __restrict__ dst, int ne) {
    int e = blockIdx.x * blockDim.x + threadIdx.x;
    if (e < ne) atomicAdd(&g_count[dst[e]], 1);
}

__global__ __launch_bounds__(SCAN_B)
void blocksum_kernel(int n) {
    int b = blockIdx.x;
    int t = threadIdx.x;
    int i = b * SCAN_B + t;
    int v = (i < n) ? g_count[i] : 0;
#pragma unroll
    for (int o = 16; o; o >>= 1) v += __shfl_xor_sync(0xffffffff, v, o);
    __shared__ int ws[SCAN_B / 32];
    int lane = t & 31, w = t >> 5;
    if (lane == 0) ws[w] = v;
    __syncthreads();
    if (t == 0) {
        int s = 0;
#pragma unroll
        for (int k = 0; k < SCAN_B / 32; k++) s += ws[k];
        g_bsum[b] = s;
    }
}

__global__ __launch_bounds__(1024)
void bscan_kernel(int nb, int n) {
    __shared__ int s[1024];
    int t = threadIdx.x;
    int v = (t < nb) ? g_bsum[t] : 0;
    s[t] = v;
    __syncthreads();
    for (int o = 1; o < 1024; o <<= 1) {
        int x = (t >= o) ? s[t - o] : 0;
        __syncthreads();
        s[t] += x;
        __syncthreads();
    }
    if (t < nb) g_bpre[t] = s[t] - v;
    if (t == 1023) g_off[n] = s[1023];
}

__global__ __launch_bounds__(SCAN_B)
void scan_blocks_kernel(int n) {
    int b = blockIdx.x;
    int t = threadIdx.x;
    int i = b * SCAN_B + t;
    int v = (i < n) ? g_count[i] : 0;

    int lane = t & 31, w = t >> 5;
    int x = v;
#pragma unroll
    for (int o = 1; o < 32; o <<= 1) {
        int y = __shfl_up_sync(0xffffffff, x, o);
        if (lane >= o) x += y;
    }
    __shared__ int ws[SCAN_B / 32];
    if (lane == 31) ws[w] = x;
    __syncthreads();
    if (w == 0) {
        int s = (lane < SCAN_B / 32) ? ws[lane] : 0;
#pragma unroll
        for (int o = 1; o < SCAN_B / 32; o <<= 1) {
            int y = __shfl_up_sync(0xffffffff, s, o);
            if (lane >= o) s += y;
        }
        if (lane < SCAN_B / 32) ws[lane] = s;
    }
    __syncthreads();
    int excl = g_bpre[b] + x + (w ? ws[w - 1] : 0) - v;
    if (i < n) { g_off[i] = excl; g_cursor[i] = excl; }
}

__global__ void scatter_kernel(const int* __restrict__ src,
                               const int* __restrict__ dst, int ne) {
    int e = blockIdx.x * blockDim.x + threadIdx.x;
    if (e < ne) {
        int pos = atomicAdd(&g_cursor[dst[e]], 1);
        g_srcs[pos] = src[e];
    }
}

// ---------------- aggregation: warp per dst node --------------------------
__global__ __launch_bounds__(256)
void aggregate_kernel(float* __restrict__ out, int n) {
    int warp = (blockIdx.x * blockDim.x + threadIdx.x) >> 5;
    int lane = threadIdx.x & 31;
    if (warp >= n) return;

    int start = g_off[warp];
    int end   = g_off[warp + 1];
    float4* orow = reinterpret_cast<float4*>(out + (size_t)warp * DD);

    if (start == end) {
        orow[lane] = make_float4(0.f, 0.f, 0.f, 0.f);
        return;
    }

    float sd = g_sdst[warp];

    float m = -INFINITY;
    for (int j = start + lane; j < end; j += 32) {
        float x = g_ssrc[g_srcs[j]] + sd;
        x = (x > 0.f) ? x : 0.01f * x;
        m = fmaxf(m, x);
    }
#pragma unroll
    for (int o = 16; o; o >>= 1) m = fmaxf(m, __shfl_xor_sync(0xffffffff, m, o));

    float denom = 0.f;
    float acc0 = 0.f, acc1 = 0.f, acc2 = 0.f, acc3 = 0.f;
#pragma unroll 4
    for (int j = start; j < end; j++) {
        int s = g_srcs[j];
        float x = g_ssrc[s] + sd;
        x = (x > 0.f) ? x : 0.01f * x;
        float w = __expf(x - m);
        denom += w;
        const uint2 hv = reinterpret_cast<const uint2*>(g_zh + (size_t)s * DD)[lane];
        __half2 h0 = *reinterpret_cast<const __half2*>(&hv.x);
        __half2 h1 = *reinterpret_cast<const __half2*>(&hv.y);
        float2 f0 = __half22float2(h0);
        float2 f1 = __half22float2(h1);
        acc0 = fmaf(w, f0.x, acc0);
        acc1 = fmaf(w, f0.y, acc1);
        acc2 = fmaf(w, f1.x, acc2);
        acc3 = fmaf(w, f1.y, acc3);
    }
    float inv = 1.0f / denom;
    orow[lane] = make_float4(acc0 * inv, acc1 * inv, acc2 * inv, acc3 * inv);
}

// ---------------- launch ---------------------------------------------------
extern "C" void kernel_launch(void* const* d_in, const int* in_sizes, int n_in,
                              void* d_out, int out_size) {
    const float* h      = (const float*)d_in[0];
    const float* W      = (const float*)d_in[1];
    const float* attn_w = (const float*)d_in[2];
    const int*   esrc   = (const int*)d_in[3];
    const int*   edst   = (const int*)d_in[4];
    float* out = (float*)d_out;

    int n  = in_sizes[0] / DD;   // 100000
    int ne = in_sizes[3];        // 1600000
    int nb = (n + SCAN_B - 1) / SCAN_B;

    // idempotent host-side attribute set (no static guards allowed)
    cudaFuncSetAttribute(gemm_kernel, cudaFuncAttributeMaxDynamicSharedMemorySize,
                         GEMM_SMEM_BYTES);

    // 1) z = h @ W (fp16 tensor cores, fused attention dots + fp16 z store)
    gemm_kernel<<<(n + 127) / 128, 256, GEMM_SMEM_BYTES>>>(h, W, attn_w, n);
    // 2) CSR build by dst
    zero_kernel<<<(n + 255) / 256, 256>>>(n);
    hist_kernel<<<(ne + 255) / 256, 256>>>(edst, ne);
    blocksum_kernel<<<nb, SCAN_B>>>(n);
    bscan_kernel<<<1, 1024>>>(nb, n);
    scan_blocks_kernel<<<nb, SCAN_B>>>(n);
    scatter_kernel<<<(ne + 255) / 256, 256>>>(esrc, edst, ne);
    // 3) softmax + weighted aggregation, warp per dst node
    aggregate_kernel<<<(n * 32 + 255) / 256, 256>>>(out, n);
}